// round 9
// baseline (speedup 1.0000x reference)
#include <cuda_runtime.h>
#include <cstdint>

// Embedding gather: out[r, :] = weight[ids[r], :]
// weight: [50257, 1024] fp32, ids: [32768] int32, out: [32768, 1024] fp32
//
// R9: L2 residency control + 256-bit loads.
// sm_103a ptxas requires .v8.b32 for ld with .L2::evict_last, so gathers are
// LDG.256 evict_last (pins the ~98MB touched weight subset in 126MB L2);
// output stores are .cs evict-first (write-once stream).
// Layout: 256 threads, 8 rows/CTA. A 4KB row = 128 x 32B slots.
//   half = tid>>7 (0/1) -> rows base+half*4 .. +3,  slot = tid&127.
// Each thread: 4 independent 32B gathers (128B in flight), then 8 x st.cs.v4.

#define THREADS 256
#define ROWS_PER_CTA 8
#define SLOTS 128          // 32B slots per 4KB row

__global__ __launch_bounds__(THREADS, 4)
void embed_gather_kernel(const float* __restrict__ weight,
                         const int* __restrict__ ids,
                         float* __restrict__ out,
                         int n_rows)
{
    const int tid  = threadIdx.x;
    const int half = tid >> 7;          // 0 or 1
    const int slot = tid & (SLOTS - 1); // 0..127
    const int base = blockIdx.x * ROWS_PER_CTA + half * 4;

    // 4 independent index loads (L1/L2-hot)
    int idx[4];
#pragma unroll
    for (int r = 0; r < 4; r++)
        idx[r] = ids[base + r];

    // 4 independent 256-bit gathers with L2 evict_last
    unsigned v[4][8];
#pragma unroll
    for (int r = 0; r < 4; r++) {
        const float* src = weight + (size_t)idx[r] * 1024 + slot * 8;
        asm volatile("ld.global.nc.L2::evict_last.v8.b32 "
                     "{%0, %1, %2, %3, %4, %5, %6, %7}, [%8];"
                     : "=r"(v[r][0]), "=r"(v[r][1]), "=r"(v[r][2]), "=r"(v[r][3]),
                       "=r"(v[r][4]), "=r"(v[r][5]), "=r"(v[r][6]), "=r"(v[r][7])
                     : "l"(src));
    }

    // streaming stores (evict-first): 2 x 16B per row handled
#pragma unroll
    for (int r = 0; r < 4; r++) {
        float* dst = out + (size_t)(base + r) * 1024 + slot * 8;
        asm volatile("st.global.cs.v4.b32 [%0], {%1, %2, %3, %4};"
                     :: "l"(dst),
                        "r"(v[r][0]), "r"(v[r][1]), "r"(v[r][2]), "r"(v[r][3])
                     : "memory");
        asm volatile("st.global.cs.v4.b32 [%0], {%1, %2, %3, %4};"
                     :: "l"(dst + 4),
                        "r"(v[r][4]), "r"(v[r][5]), "r"(v[r][6]), "r"(v[r][7])
                     : "memory");
    }
}

extern "C" void kernel_launch(void* const* d_in, const int* in_sizes, int n_in,
                              void* d_out, int out_size)
{
    // Identify inputs by element count:
    //   weight: 50257*1024 = 51463168 elements; ids: 32768 elements
    const float* weight;
    const int* ids;
    int n_rows;

    if (in_sizes[0] > in_sizes[1]) {
        weight = (const float*)d_in[0];
        ids    = (const int*)d_in[1];
        n_rows = in_sizes[1];
    } else {
        weight = (const float*)d_in[1];
        ids    = (const int*)d_in[0];
        n_rows = in_sizes[0];
    }

    int n_blocks = n_rows / ROWS_PER_CTA;  // 32768/8 = 4096, exact
    embed_gather_kernel<<<n_blocks, THREADS>>>(weight, ids, (float*)d_out, n_rows);
}

// round 10
// speedup vs baseline: 1.0722x; 1.0722x over previous
#include <cuda_runtime.h>
#include <cstdint>

// Embedding gather: out[r, :] = weight[ids[r], :]
// weight: [50257, 1024] fp32, ids: [32768] int32, out: [32768, 1024] fp32
//
// R10: R6 shape (best: 8 rows/CTA, 256 thr, compiler-scheduled 16B gathers,
// regs~32, occ~79%) + L2 evict_last applied via createpolicy/cache_hint,
// which — unlike the bare .L2::evict_last modifier — is legal on .v4.f32.
// This isolates the residency hint from R9's harmful 256-bit load shape.
// Stores remain .cs (evict-first write-once stream).

#define DIM4 256          // DIM/4 float4 per row
#define THREADS 256
#define ROWS_PER_CTA 8

__global__ __launch_bounds__(THREADS)
void embed_gather_kernel(const float4* __restrict__ weight,
                         const int* __restrict__ ids,
                         float4* __restrict__ out,
                         int n_rows)
{
    const int tid  = threadIdx.x;
    const int base = blockIdx.x * ROWS_PER_CTA;

    // L2 policy: evict_last for the gathered weight rows
    uint64_t policy;
    asm("createpolicy.fractional.L2::evict_last.b64 %0, 1.0;" : "=l"(policy));

    // 8 independent broadcast index loads
    int idx[ROWS_PER_CTA];
#pragma unroll
    for (int r = 0; r < ROWS_PER_CTA; r++)
        idx[r] = ids[base + r];

    // 8 independent 16B gathers with evict_last cache hint.
    // Plain (non-volatile) asm so ptxas may schedule/wave them like R6.
    float v[ROWS_PER_CTA][4];
#pragma unroll
    for (int r = 0; r < ROWS_PER_CTA; r++) {
        const float4* src = weight + (size_t)idx[r] * DIM4 + tid;
        asm("ld.global.nc.L2::cache_hint.v4.f32 {%0, %1, %2, %3}, [%4], %5;"
            : "=f"(v[r][0]), "=f"(v[r][1]), "=f"(v[r][2]), "=f"(v[r][3])
            : "l"(src), "l"(policy));
    }

    // 8 streaming stores
#pragma unroll
    for (int r = 0; r < ROWS_PER_CTA; r++) {
        float4* dst = out + (size_t)(base + r) * DIM4 + tid;
        asm volatile("st.global.cs.v4.f32 [%0], {%1, %2, %3, %4};"
                     :: "l"(dst),
                        "f"(v[r][0]), "f"(v[r][1]), "f"(v[r][2]), "f"(v[r][3])
                     : "memory");
    }
}

extern "C" void kernel_launch(void* const* d_in, const int* in_sizes, int n_in,
                              void* d_out, int out_size)
{
    // Identify inputs by element count:
    //   weight: 50257*1024 = 51463168 elements; ids: 32768 elements
    const float4* weight;
    const int* ids;
    int n_rows;

    if (in_sizes[0] > in_sizes[1]) {
        weight = (const float4*)d_in[0];
        ids    = (const int*)d_in[1];
        n_rows = in_sizes[1];
    } else {
        weight = (const float4*)d_in[1];
        ids    = (const int*)d_in[0];
        n_rows = in_sizes[0];
    }

    int n_blocks = n_rows / ROWS_PER_CTA;  // 32768/8 = 4096, exact
    embed_gather_kernel<<<n_blocks, THREADS>>>(weight, ids, (float4*)d_out, n_rows);
}